// round 1
// baseline (speedup 1.0000x reference)
#include <cuda_runtime.h>
#include <cuda_bf16.h>
#include <math.h>

#define Bb 16
#define Cc 256
#define Tt 8192
#define Ee 32
#define SPLIT 8

// ---- scratch (device globals: no allocation allowed) ----
__device__ float g_mean[Bb * Tt];
__device__ float g_var[Bb * Tt];
__device__ float g_invdenom[Bb];
__device__ float g_part[SPLIT][Bb * Cc * Cc];   // split-K partials for cov
__device__ float g_pcc[Bb * Cc * Cc];
__device__ float g_q[Bb * Cc * Ee];
__device__ float g_k[Bb * Cc * Ee];

// ---------------------------------------------------------------------------
// 1) per-(b,t) column stats over channel dim: mean, unbiased variance
// ---------------------------------------------------------------------------
__global__ void stats_kernel(const float* __restrict__ x) {
    int b = blockIdx.y;
    int t = blockIdx.x * blockDim.x + threadIdx.x;
    const float* xp = x + (size_t)b * Cc * Tt + t;
    float s = 0.f, sq = 0.f;
#pragma unroll 8
    for (int c = 0; c < Cc; c++) {
        float v = xp[(size_t)c * Tt];
        s += v;
        sq += v * v;
    }
    float m = s * (1.0f / Cc);
    g_mean[b * Tt + t] = m;
    g_var[b * Tt + t] = (sq - (float)Cc * m * m) * (1.0f / (Cc - 1));  // ddof=1
}

// ---------------------------------------------------------------------------
// 2) denom[b] = sum_t var[b,t]; store reciprocal
// ---------------------------------------------------------------------------
__global__ void denom_kernel() {
    int b = blockIdx.x, tid = threadIdx.x;
    __shared__ float red[256];
    float a = 0.f;
    for (int t = tid; t < Tt; t += 256) a += g_var[b * Tt + t];
    red[tid] = a;
    __syncthreads();
    for (int o = 128; o > 0; o >>= 1) {
        if (tid < o) red[tid] += red[tid + o];
        __syncthreads();
    }
    if (tid == 0) g_invdenom[b] = 1.0f / red[0];
}

// ---------------------------------------------------------------------------
// 3) cov split-K GEMM: part[s][b,c,d] = sum_{t in split s} (x[c,t]-m[t])(x[d,t]-m[t])
//    128x128 tile, BK=32, 256 threads, 8x8 per-thread microtile.
// ---------------------------------------------------------------------------
__global__ void __launch_bounds__(256) cov_kernel(const float* __restrict__ x) {
    __shared__ float As[32][132];
    __shared__ float Bs[32][132];
    int b = blockIdx.z >> 3;
    int s = blockIdx.z & 7;
    int cm = blockIdx.y * 128;
    int cn = blockIdx.x * 128;
    const float* xb = x + (size_t)b * Cc * Tt;
    const float* mb = g_mean + b * Tt;
    int tid = threadIdx.x;
    int lr = tid >> 3;   // 0..31
    int lq = tid & 7;    // float4 slot over t
    int tx = tid & 15, ty = tid >> 4;

    float acc[8][8];
#pragma unroll
    for (int i = 0; i < 8; i++)
#pragma unroll
        for (int j = 0; j < 8; j++) acc[i][j] = 0.f;

    int k0s = s * (Tt / SPLIT);
    for (int k0 = k0s; k0 < k0s + Tt / SPLIT; k0 += 32) {
        float4 m4 = *(const float4*)&mb[k0 + lq * 4];
#pragma unroll
        for (int i = 0; i < 4; i++) {
            int r = lr + i * 32;
            float4 v = *(const float4*)&xb[(size_t)(cm + r) * Tt + k0 + lq * 4];
            As[lq * 4 + 0][r] = v.x - m4.x;
            As[lq * 4 + 1][r] = v.y - m4.y;
            As[lq * 4 + 2][r] = v.z - m4.z;
            As[lq * 4 + 3][r] = v.w - m4.w;
            float4 w = *(const float4*)&xb[(size_t)(cn + r) * Tt + k0 + lq * 4];
            Bs[lq * 4 + 0][r] = w.x - m4.x;
            Bs[lq * 4 + 1][r] = w.y - m4.y;
            Bs[lq * 4 + 2][r] = w.z - m4.z;
            Bs[lq * 4 + 3][r] = w.w - m4.w;
        }
        __syncthreads();
#pragma unroll
        for (int k = 0; k < 32; k++) {
            float a[8], bbv[8];
            *(float4*)(a) = *(const float4*)&As[k][ty * 8];
            *(float4*)(a + 4) = *(const float4*)&As[k][ty * 8 + 4];
            *(float4*)(bbv) = *(const float4*)&Bs[k][tx * 8];
            *(float4*)(bbv + 4) = *(const float4*)&Bs[k][tx * 8 + 4];
#pragma unroll
            for (int i = 0; i < 8; i++)
#pragma unroll
                for (int j = 0; j < 8; j++) acc[i][j] += a[i] * bbv[j];
        }
        __syncthreads();
    }
    float* dst = g_part[s] + (size_t)b * Cc * Cc;
#pragma unroll
    for (int i = 0; i < 8; i++) {
        int c = cm + ty * 8 + i;
#pragma unroll
        for (int j = 0; j < 8; j += 4) {
            float4 v = make_float4(acc[i][j], acc[i][j + 1], acc[i][j + 2], acc[i][j + 3]);
            *(float4*)&dst[(size_t)c * Cc + cn + tx * 8 + j] = v;
        }
    }
}

// ---------------------------------------------------------------------------
// 4) pcc = (sum_s part[s]) / denom[b]
// ---------------------------------------------------------------------------
__global__ void pcc_kernel() {
    int idx = blockIdx.x * 256 + threadIdx.x;  // n = B*C*C = 1048576
    float a = 0.f;
#pragma unroll
    for (int s = 0; s < SPLIT; s++) a += g_part[s][idx];
    int b = idx >> 16;  // C*C = 65536
    g_pcc[idx] = a * g_invdenom[b];
}

// ---------------------------------------------------------------------------
// 5) q = pcc @ q_w^T + q_b ; k = pcc @ k_w^T + k_b   (N=64 combined)
//    64x64 tile, BK=32, 256 threads, 4x4 per thread.
// ---------------------------------------------------------------------------
__global__ void __launch_bounds__(256) qk_kernel(const float* __restrict__ qw,
                                                 const float* __restrict__ qb,
                                                 const float* __restrict__ kw,
                                                 const float* __restrict__ kb) {
    __shared__ float Ps[32][68];
    __shared__ float Ws[32][68];
    int b = blockIdx.y;
    int c0 = blockIdx.x * 64;
    int tid = threadIdx.x;
    int lr = tid >> 3, lq = tid & 7;
    int tx = tid & 15, ty = tid >> 4;
    const float* pb = g_pcc + (size_t)b * Cc * Cc;

    float acc[4][4];
#pragma unroll
    for (int i = 0; i < 4; i++)
#pragma unroll
        for (int j = 0; j < 4; j++) acc[i][j] = 0.f;

    for (int d0 = 0; d0 < Cc; d0 += 32) {
#pragma unroll
        for (int i = 0; i < 2; i++) {
            int r = lr + i * 32;  // 0..63
            float4 v = *(const float4*)&pb[(size_t)(c0 + r) * Cc + d0 + lq * 4];
            Ps[lq * 4 + 0][r] = v.x;
            Ps[lq * 4 + 1][r] = v.y;
            Ps[lq * 4 + 2][r] = v.z;
            Ps[lq * 4 + 3][r] = v.w;
            const float* wsrc = (r < 32) ? (qw + (size_t)r * Cc) : (kw + (size_t)(r - 32) * Cc);
            float4 w = *(const float4*)&wsrc[d0 + lq * 4];
            Ws[lq * 4 + 0][r] = w.x;
            Ws[lq * 4 + 1][r] = w.y;
            Ws[lq * 4 + 2][r] = w.z;
            Ws[lq * 4 + 3][r] = w.w;
        }
        __syncthreads();
#pragma unroll
        for (int k = 0; k < 32; k++) {
            float a[4], bbv[4];
            *(float4*)(a) = *(const float4*)&Ps[k][ty * 4];
            *(float4*)(bbv) = *(const float4*)&Ws[k][tx * 4];
#pragma unroll
            for (int i = 0; i < 4; i++)
#pragma unroll
                for (int j = 0; j < 4; j++) acc[i][j] += a[i] * bbv[j];
        }
        __syncthreads();
    }
#pragma unroll
    for (int i = 0; i < 4; i++) {
        int c = c0 + ty * 4 + i;
#pragma unroll
        for (int j = 0; j < 4; j++) {
            int e = tx * 4 + j;
            if (e < 32)
                g_q[((size_t)b * Cc + c) * Ee + e] = acc[i][j] + qb[e];
            else
                g_k[((size_t)b * Cc + c) * Ee + (e - 32)] = acc[i][j] + kb[e - 32];
        }
    }
}

// ---------------------------------------------------------------------------
// 6) scores = q k^T / 16, row softmax -> attn (written straight to d_out region)
//    block = (b, 16 c-rows); thread = one d column.
// ---------------------------------------------------------------------------
__global__ void __launch_bounds__(256) attn_kernel(float* __restrict__ attn_out) {
    __shared__ float ks[Cc * 33];
    __shared__ float qs[16 * Ee];
    __shared__ float red[256];
    int b = blockIdx.y;
    int c0 = blockIdx.x * 16;
    int tid = threadIdx.x;

    const float* kbp = g_k + (size_t)b * Cc * Ee;
    for (int idx = tid; idx < Cc * Ee; idx += 256) {
        int d = idx >> 5, e = idx & 31;
        ks[d * 33 + e] = kbp[idx];
    }
    const float* qbp = g_q + (size_t)b * Cc * Ee + (size_t)c0 * Ee;
    for (int idx = tid; idx < 16 * Ee; idx += 256) qs[idx] = qbp[idx];
    __syncthreads();

    float* ab = attn_out + (size_t)b * Cc * Cc;
    for (int r = 0; r < 16; r++) {
        float sv = 0.f;
#pragma unroll
        for (int e = 0; e < Ee; e++) sv += qs[r * Ee + e] * ks[tid * 33 + e];
        sv *= 0.0625f;  // 1/sqrt(256)

        red[tid] = sv;
        __syncthreads();
        for (int o = 128; o > 0; o >>= 1) {
            if (tid < o) red[tid] = fmaxf(red[tid], red[tid + o]);
            __syncthreads();
        }
        float mx = red[0];
        __syncthreads();

        float p = expf(sv - mx);
        red[tid] = p;
        __syncthreads();
        for (int o = 128; o > 0; o >>= 1) {
            if (tid < o) red[tid] += red[tid + o];
            __syncthreads();
        }
        float inv = 1.0f / red[0];
        __syncthreads();

        ab[(size_t)(c0 + r) * Cc + tid] = p * inv;
    }
}

// ---------------------------------------------------------------------------
// 7) out = attn @ x   (128x128 tile, BK=32, 8x8 per thread)
// ---------------------------------------------------------------------------
__global__ void __launch_bounds__(256) out_kernel(const float* __restrict__ x,
                                                  const float* __restrict__ attn,
                                                  float* __restrict__ out) {
    __shared__ float As[32][132];
    __shared__ float Bs[32][132];
    int b = blockIdx.z;
    int cm = blockIdx.y * 128;
    int tn = blockIdx.x * 128;
    int tid = threadIdx.x;
    int tx = tid & 15, ty = tid >> 4;
    const float* ab = attn + (size_t)b * Cc * Cc;
    const float* xb = x + (size_t)b * Cc * Tt;

    float acc[8][8];
#pragma unroll
    for (int i = 0; i < 8; i++)
#pragma unroll
        for (int j = 0; j < 8; j++) acc[i][j] = 0.f;

    for (int d0 = 0; d0 < Cc; d0 += 32) {
        {  // attn tile [128 c x 32 d] -> transposed As[d][c]
            int lr = tid >> 3, lq = tid & 7;
#pragma unroll
            for (int i = 0; i < 4; i++) {
                int r = lr + i * 32;
                float4 v = *(const float4*)&ab[(size_t)(cm + r) * Cc + d0 + lq * 4];
                As[lq * 4 + 0][r] = v.x;
                As[lq * 4 + 1][r] = v.y;
                As[lq * 4 + 2][r] = v.z;
                As[lq * 4 + 3][r] = v.w;
            }
        }
        {  // x tile [32 d x 128 t] -> Bs[d][t]
            int rr = tid >> 5;   // 0..7
            int cq = tid & 31;   // float4 slot over t
#pragma unroll
            for (int i = 0; i < 4; i++) {
                int d = rr + i * 8;
                float4 v = *(const float4*)&xb[(size_t)(d0 + d) * Tt + tn + cq * 4];
                *(float4*)&Bs[d][cq * 4] = v;
            }
        }
        __syncthreads();
#pragma unroll
        for (int k = 0; k < 32; k++) {
            float a[8], bbv[8];
            *(float4*)(a) = *(const float4*)&As[k][ty * 8];
            *(float4*)(a + 4) = *(const float4*)&As[k][ty * 8 + 4];
            *(float4*)(bbv) = *(const float4*)&Bs[k][tx * 8];
            *(float4*)(bbv + 4) = *(const float4*)&Bs[k][tx * 8 + 4];
#pragma unroll
            for (int i = 0; i < 8; i++)
#pragma unroll
                for (int j = 0; j < 8; j++) acc[i][j] += a[i] * bbv[j];
        }
        __syncthreads();
    }
    float* ob = out + (size_t)b * Cc * Tt;
#pragma unroll
    for (int i = 0; i < 8; i++) {
        int c = cm + ty * 8 + i;
#pragma unroll
        for (int j = 0; j < 8; j += 4) {
            float4 v = make_float4(acc[i][j], acc[i][j + 1], acc[i][j + 2], acc[i][j + 3]);
            *(float4*)&ob[(size_t)c * Tt + tn + tx * 8 + j] = v;
        }
    }
}

// ---------------------------------------------------------------------------
extern "C" void kernel_launch(void* const* d_in, const int* in_sizes, int n_in,
                              void* d_out, int out_size) {
    const float* x = (const float*)d_in[0];
    const float* qw = (const float*)d_in[1];
    const float* qb = (const float*)d_in[2];
    const float* kw = (const float*)d_in[3];
    const float* kb = (const float*)d_in[4];
    float* out = (float*)d_out;
    float* attn = out + (size_t)Bb * Cc * Tt;  // outputs packed: (out, attn)

    stats_kernel<<<dim3(Tt / 256, Bb), 256>>>(x);
    denom_kernel<<<Bb, 256>>>();
    cov_kernel<<<dim3(2, 2, Bb * SPLIT), 256>>>(x);
    pcc_kernel<<<(Bb * Cc * Cc) / 256, 256>>>();
    qk_kernel<<<dim3(Cc / 64, Bb), 256>>>(qw, qb, kw, kb);
    attn_kernel<<<dim3(Cc / 16, Bb), 256>>>(attn);
    out_kernel<<<dim3(Tt / 128, Cc / 128, Bb), 256>>>(x, attn, out);
}

// round 4
// speedup vs baseline: 1.4899x; 1.4899x over previous
#include <cuda_runtime.h>
#include <cuda_bf16.h>
#include <cstdint>
#include <math.h>

#define Bb 16
#define Cc 256
#define Tt 8192
#define Ee 32
#define SPLIT 2

// ===== scratch (device globals; no allocation allowed) =====
__device__ float g_mean[Bb * Tt];
__device__ float g_var[Bb * Tt];
__device__ float g_invdenom[Bb];
__device__ float g_part[SPLIT][Bb * Cc * Cc];
__device__ float g_pcc[Bb * Cc * Cc];
__device__ float g_q[Bb * Cc * Ee];
__device__ float g_k[Bb * Cc * Ee];
__device__ __nv_bfloat16 g_cthi[Bb * Cc * Tt];    // centered x, t-major, hi
__device__ __nv_bfloat16 g_ctlo[Bb * Cc * Tt];    // centered x, t-major, lo
__device__ __nv_bfloat16 g_cthiT[Bb * Tt * Cc];   // centered x, c-major (transposed), hi
__device__ __nv_bfloat16 g_ctloT[Bb * Tt * Cc];   // centered x, c-major, lo
__device__ __nv_bfloat16 g_ahi[Bb * Cc * Cc];     // attn hi
__device__ __nv_bfloat16 g_alo[Bb * Cc * Cc];     // attn lo

// ===== helpers =====
__device__ __forceinline__ uint32_t smem_u32(const void* p) {
    uint32_t a;
    asm("{ .reg .u64 t; cvta.to.shared.u64 t, %1; cvt.u32.u64 %0, t; }" : "=r"(a) : "l"(p));
    return a;
}
#define CP_ASYNC16(dst, src) \
    asm volatile("cp.async.cg.shared.global [%0], [%1], 16;" :: "r"(dst), "l"(src))
#define CP_COMMIT() asm volatile("cp.async.commit_group;" ::: "memory")
#define CP_WAIT1() asm volatile("cp.async.wait_group 1;" ::: "memory")
#define CP_WAIT0() asm volatile("cp.async.wait_group 0;" ::: "memory")

#define LDMATRIX_X4(r0, r1, r2, r3, a) \
    asm volatile("ldmatrix.sync.aligned.m8n8.x4.shared.b16 {%0,%1,%2,%3}, [%4];" \
        : "=r"(r0), "=r"(r1), "=r"(r2), "=r"(r3) : "r"(a))

#define MMA16816(c0, c1, c2, c3, a0, a1, a2, a3, b0, b1) \
    asm volatile("mma.sync.aligned.m16n8k16.row.col.f32.bf16.bf16.f32 " \
        "{%0,%1,%2,%3}, {%4,%5,%6,%7}, {%8,%9}, {%0,%1,%2,%3};" \
        : "+f"(c0), "+f"(c1), "+f"(c2), "+f"(c3) \
        : "r"(a0), "r"(a1), "r"(a2), "r"(a3), "r"(b0), "r"(b1))

// smem tile: 128 rows x 32 bf16, row stride 80B (64B data + 16B pad -> conflict-free ldmatrix)
#define ROWB 80
#define TILEB (128 * ROWB)       // 10240
#define STAGEB (2 * TILEB)       // A + B per stage
#define NSTAGE 3
#define SMEM_DYN (NSTAGE * STAGEB)

// load one 128x32 bf16 tile (K-major, rowStride elems) into smem at sbuf
__device__ __forceinline__ void load_tile(uint32_t sbuf, const __nv_bfloat16* gbase,
                                          size_t rowStride, int tid) {
#pragma unroll
    for (int i = tid; i < 512; i += 256) {
        int r = i >> 2, s = i & 3;
        CP_ASYNC16(sbuf + r * ROWB + s * 16, gbase + (size_t)r * rowStride + s * 8);
    }
}

// ---------------------------------------------------------------------------
// 1) stats + centered bf16 hi/lo emission (both layouts), 32 t x 256 c tiles
// ---------------------------------------------------------------------------
__global__ void __launch_bounds__(256) stats_tr_kernel(const float* __restrict__ x) {
    __shared__ float xs[Cc][33];
    __shared__ float ms[32];
    int b = blockIdx.y;
    int t0 = blockIdx.x * 32;
    int tid = threadIdx.x;

    for (int idx = tid; idx < Cc * 32; idx += 256) {
        int c = idx >> 5, tt = idx & 31;
        xs[c][tt] = x[((size_t)(b * Cc + c)) * Tt + t0 + tt];
    }
    __syncthreads();
    if (tid < 32) {
        float s = 0.f, sq = 0.f;
#pragma unroll 8
        for (int c = 0; c < Cc; c++) {
            float v = xs[c][tid];
            s += v; sq += v * v;
        }
        float m = s * (1.0f / Cc);
        ms[tid] = m;
        g_mean[b * Tt + t0 + tid] = m;
        g_var[b * Tt + t0 + tid] = (sq - (float)Cc * m * m) * (1.0f / (Cc - 1));
    }
    __syncthreads();
    // t-major centered hi/lo
    for (int idx = tid; idx < Cc * 32; idx += 256) {
        int c = idx >> 5, tt = idx & 31;
        float v = xs[c][tt] - ms[tt];
        __nv_bfloat16 h = __float2bfloat16(v);
        size_t o = ((size_t)(b * Cc + c)) * Tt + t0 + tt;
        g_cthi[o] = h;
        g_ctlo[o] = __float2bfloat16(v - __bfloat162float(h));
    }
    // c-major (transposed) centered hi/lo
    for (int idx = tid; idx < Cc * 32; idx += 256) {
        int tt = idx >> 8, c = idx & 255;
        float v = xs[c][tt] - ms[tt];
        __nv_bfloat16 h = __float2bfloat16(v);
        size_t o = ((size_t)(b * Tt + t0 + tt)) * Cc + c;
        g_cthiT[o] = h;
        g_ctloT[o] = __float2bfloat16(v - __bfloat162float(h));
    }
}

// ---------------------------------------------------------------------------
// 2) denom
// ---------------------------------------------------------------------------
__global__ void denom_kernel() {
    int b = blockIdx.x, tid = threadIdx.x;
    __shared__ float red[256];
    float a = 0.f;
    for (int t = tid; t < Tt; t += 256) a += g_var[b * Tt + t];
    red[tid] = a;
    __syncthreads();
    for (int o = 128; o > 0; o >>= 1) {
        if (tid < o) red[tid] += red[tid + o];
        __syncthreads();
    }
    if (tid == 0) g_invdenom[b] = 1.0f / red[0];
}

// ---------------------------------------------------------------------------
// 3) cov via mma.sync bf16 3-term: part[s] = ct_cm ct_cn^T over split-K
//    CTA: 128x128, 8 warps 2x4 (warp 64x32), BK=32, 3-stage cp.async pipeline
// ---------------------------------------------------------------------------
__global__ void __launch_bounds__(256, 1) cov_mma_kernel() {
    extern __shared__ char dynsmem[];
    uint32_t base = smem_u32(dynsmem);
    int tid = threadIdx.x;
    int lane = tid & 31, wid = tid >> 5;
    int b = blockIdx.z >> 1;
    int sp = blockIdx.z & 1;
    int cm = blockIdx.y * 128;
    int cn = blockIdx.x * 128;
    int m0 = (wid & 1) * 64;
    int n0 = (wid >> 1) * 32;
    const int k0 = sp * (Tt / SPLIT);
    const int NSEG = (Tt / SPLIT) / 32;   // 128 chunks per segment
    const int NST = 3 * NSEG;

    const __nv_bfloat16* segA[3] = {g_cthi, g_cthi, g_ctlo};
    const __nv_bfloat16* segB[3] = {g_cthi, g_ctlo, g_cthi};

    float acc[4][4][4];
#pragma unroll
    for (int i = 0; i < 4; i++)
#pragma unroll
        for (int j = 0; j < 4; j++)
#pragma unroll
            for (int k = 0; k < 4; k++) acc[i][j][k] = 0.f;

    // prologue: stages 0,1
#pragma unroll
    for (int p = 0; p < 2; p++) {
        int seg = p / NSEG;  // p<2 -> seg 0
        int kb = k0 + (p % NSEG) * 32;
        load_tile(base + p * STAGEB, segA[seg] + ((size_t)(b * Cc + cm)) * Tt + kb, Tt, tid);
        load_tile(base + p * STAGEB + TILEB, segB[seg] + ((size_t)(b * Cc + cn)) * Tt + kb, Tt, tid);
        CP_COMMIT();
    }

    int stg = 0;
    for (int ch = 0; ch < NST; ch++) {
        if (ch == NST - 1) { CP_WAIT0(); } else { CP_WAIT1(); }
        __syncthreads();
        if (ch + 2 < NST) {
            int nc = ch + 2;
            int seg = nc / NSEG;
            int kb = k0 + (nc % NSEG) * 32;
            int ns = (stg + 2 >= NSTAGE) ? (stg + 2 - NSTAGE) : (stg + 2);
            load_tile(base + ns * STAGEB, segA[seg] + ((size_t)(b * Cc + cm)) * Tt + kb, Tt, tid);
            load_tile(base + ns * STAGEB + TILEB, segB[seg] + ((size_t)(b * Cc + cn)) * Tt + kb, Tt, tid);
            CP_COMMIT();
        }
        uint32_t abuf = base + stg * STAGEB;
        uint32_t bbuf = abuf + TILEB;
#pragma unroll
        for (int ks = 0; ks < 2; ks++) {
            uint32_t a[4][4], bf[2][4];
#pragma unroll
            for (int mi = 0; mi < 4; mi++) {
                uint32_t ad = abuf + (m0 + mi * 16 + (lane & 15)) * ROWB + ks * 32 + ((lane >> 4) << 4);
                LDMATRIX_X4(a[mi][0], a[mi][1], a[mi][2], a[mi][3], ad);
            }
#pragma unroll
            for (int np = 0; np < 2; np++) {
                uint32_t bd = bbuf + (n0 + np * 16 + (lane & 7) + ((lane >> 4) << 3)) * ROWB +
                              ks * 32 + (((lane >> 3) & 1) << 4);
                LDMATRIX_X4(bf[np][0], bf[np][1], bf[np][2], bf[np][3], bd);
            }
#pragma unroll
            for (int mi = 0; mi < 4; mi++)
#pragma unroll
                for (int ni = 0; ni < 4; ni++) {
                    int np = ni >> 1, pp = (ni & 1) << 1;
                    MMA16816(acc[mi][ni][0], acc[mi][ni][1], acc[mi][ni][2], acc[mi][ni][3],
                             a[mi][0], a[mi][1], a[mi][2], a[mi][3], bf[np][pp], bf[np][pp + 1]);
                }
        }
        stg = (stg + 1 == NSTAGE) ? 0 : stg + 1;
    }

    float* dst = g_part[sp] + ((size_t)b) * Cc * Cc;
#pragma unroll
    for (int mi = 0; mi < 4; mi++)
#pragma unroll
        for (int ni = 0; ni < 4; ni++) {
            int row = cm + m0 + mi * 16 + (lane >> 2);
            int col = cn + n0 + ni * 8 + ((lane & 3) << 1);
            *(float2*)&dst[(size_t)row * Cc + col] = make_float2(acc[mi][ni][0], acc[mi][ni][1]);
            *(float2*)&dst[(size_t)(row + 8) * Cc + col] = make_float2(acc[mi][ni][2], acc[mi][ni][3]);
        }
}

// ---------------------------------------------------------------------------
// 4) pcc = (sum_s part[s]) * invdenom[b]
// ---------------------------------------------------------------------------
__global__ void pcc_kernel() {
    int idx = blockIdx.x * 256 + threadIdx.x;
    float a = 0.f;
#pragma unroll
    for (int s = 0; s < SPLIT; s++) a += g_part[s][idx];
    int b = idx >> 16;
    g_pcc[idx] = a * g_invdenom[b];
}

// ---------------------------------------------------------------------------
// 5) q/k projections (small fp32 SIMT GEMM)
// ---------------------------------------------------------------------------
__global__ void __launch_bounds__(256) qk_kernel(const float* __restrict__ qw,
                                                 const float* __restrict__ qb,
                                                 const float* __restrict__ kw,
                                                 const float* __restrict__ kb) {
    __shared__ float Ps[32][68];
    __shared__ float Ws[32][68];
    int b = blockIdx.y;
    int c0 = blockIdx.x * 64;
    int tid = threadIdx.x;
    int lr = tid >> 3, lq = tid & 7;
    int tx = tid & 15, ty = tid >> 4;
    const float* pb = g_pcc + (size_t)b * Cc * Cc;

    float acc[4][4];
#pragma unroll
    for (int i = 0; i < 4; i++)
#pragma unroll
        for (int j = 0; j < 4; j++) acc[i][j] = 0.f;

    for (int d0 = 0; d0 < Cc; d0 += 32) {
#pragma unroll
        for (int i = 0; i < 2; i++) {
            int r = lr + i * 32;
            float4 v = *(const float4*)&pb[(size_t)(c0 + r) * Cc + d0 + lq * 4];
            Ps[lq * 4 + 0][r] = v.x; Ps[lq * 4 + 1][r] = v.y;
            Ps[lq * 4 + 2][r] = v.z; Ps[lq * 4 + 3][r] = v.w;
            const float* wsrc = (r < 32) ? (qw + (size_t)r * Cc) : (kw + (size_t)(r - 32) * Cc);
            float4 w = *(const float4*)&wsrc[d0 + lq * 4];
            Ws[lq * 4 + 0][r] = w.x; Ws[lq * 4 + 1][r] = w.y;
            Ws[lq * 4 + 2][r] = w.z; Ws[lq * 4 + 3][r] = w.w;
        }
        __syncthreads();
#pragma unroll
        for (int k = 0; k < 32; k++) {
            float a[4], bbv[4];
            *(float4*)(a) = *(const float4*)&Ps[k][ty * 4];
            *(float4*)(bbv) = *(const float4*)&Ws[k][tx * 4];
#pragma unroll
            for (int i = 0; i < 4; i++)
#pragma unroll
                for (int j = 0; j < 4; j++) acc[i][j] += a[i] * bbv[j];
        }
        __syncthreads();
    }
#pragma unroll
    for (int i = 0; i < 4; i++) {
        int c = c0 + ty * 4 + i;
#pragma unroll
        for (int j = 0; j < 4; j++) {
            int e = tx * 4 + j;
            if (e < 32) g_q[((size_t)b * Cc + c) * Ee + e] = acc[i][j] + qb[e];
            else g_k[((size_t)b * Cc + c) * Ee + (e - 32)] = acc[i][j] + kb[e - 32];
        }
    }
}

// ---------------------------------------------------------------------------
// 6) scores -> softmax -> attn (fp32 to d_out) + bf16 hi/lo for out GEMM
// ---------------------------------------------------------------------------
__global__ void __launch_bounds__(256) attn_kernel(float* __restrict__ attn_out) {
    __shared__ float ks[Cc * 33];
    __shared__ float qs[16 * Ee];
    __shared__ float red[256];
    int b = blockIdx.y;
    int c0 = blockIdx.x * 16;
    int tid = threadIdx.x;

    const float* kbp = g_k + (size_t)b * Cc * Ee;
    for (int idx = tid; idx < Cc * Ee; idx += 256) {
        int d = idx >> 5, e = idx & 31;
        ks[d * 33 + e] = kbp[idx];
    }
    const float* qbp = g_q + (size_t)b * Cc * Ee + (size_t)c0 * Ee;
    for (int idx = tid; idx < 16 * Ee; idx += 256) qs[idx] = qbp[idx];
    __syncthreads();

    float* ab = attn_out + (size_t)b * Cc * Cc;
    for (int r = 0; r < 16; r++) {
        float sv = 0.f;
#pragma unroll
        for (int e = 0; e < Ee; e++) sv += qs[r * Ee + e] * ks[tid * 33 + e];
        sv *= 0.0625f;

        red[tid] = sv;
        __syncthreads();
        for (int o = 128; o > 0; o >>= 1) {
            if (tid < o) red[tid] = fmaxf(red[tid], red[tid + o]);
            __syncthreads();
        }
        float mx = red[0];
        __syncthreads();
        float p = expf(sv - mx);
        red[tid] = p;
        __syncthreads();
        for (int o = 128; o > 0; o >>= 1) {
            if (tid < o) red[tid] += red[tid + o];
            __syncthreads();
        }
        float inv = 1.0f / red[0];
        __syncthreads();

        float av = p * inv;
        size_t oidx = (size_t)(c0 + r) * Cc + tid;
        ab[oidx] = av;
        __nv_bfloat16 h = __float2bfloat16(av);
        g_ahi[(size_t)b * Cc * Cc + oidx] = h;
        g_alo[(size_t)b * Cc * Cc + oidx] = __float2bfloat16(av - __bfloat162float(h));
    }
}

// ---------------------------------------------------------------------------
// 7) out via mma.sync: out[c, t] = sum_d attn[c,d] ctT[t,d] + mean[t]
//    A = attn (M=c, K=d), B = ctT (N=t, K=d). CTA 128x128, K=256 x 3 segs.
// ---------------------------------------------------------------------------
__global__ void __launch_bounds__(256, 1) out_mma_kernel(float* __restrict__ out) {
    extern __shared__ char dynsmem[];
    uint32_t base = smem_u32(dynsmem);
    int tid = threadIdx.x;
    int lane = tid & 31, wid = tid >> 5;
    int b = blockIdx.z;
    int cm = blockIdx.y * 128;
    int t0 = blockIdx.x * 128;
    int m0 = (wid & 1) * 64;
    int n0 = (wid >> 1) * 32;
    const int NST = 24;  // 3 segs x 8 chunks of 32 over K=256

    const __nv_bfloat16* segA[3] = {g_ahi, g_ahi, g_alo};
    const __nv_bfloat16* segB[3] = {g_cthiT, g_ctloT, g_cthiT};

    float acc[4][4][4];
#pragma unroll
    for (int i = 0; i < 4; i++)
#pragma unroll
        for (int j = 0; j < 4; j++)
#pragma unroll
            for (int k = 0; k < 4; k++) acc[i][j][k] = 0.f;

#pragma unroll
    for (int p = 0; p < 2; p++) {
        int seg = p >> 3;
        int kb = (p & 7) * 32;
        load_tile(base + p * STAGEB, segA[seg] + ((size_t)(b * Cc + cm)) * Cc + kb, Cc, tid);
        load_tile(base + p * STAGEB + TILEB, segB[seg] + ((size_t)(b * Tt + t0)) * Cc + kb, Cc, tid);
        CP_COMMIT();
    }

    int stg = 0;
    for (int ch = 0; ch < NST; ch++) {
        if (ch == NST - 1) { CP_WAIT0(); } else { CP_WAIT1(); }
        __syncthreads();
        if (ch + 2 < NST) {
            int nc = ch + 2;
            int seg = nc >> 3;
            int kb = (nc & 7) * 32;
            int ns = (stg + 2 >= NSTAGE) ? (stg + 2 - NSTAGE) : (stg + 2);
            load_tile(base + ns * STAGEB, segA[seg] + ((size_t)(b * Cc + cm)) * Cc + kb, Cc, tid);
            load_tile(base + ns * STAGEB + TILEB, segB[seg] + ((size_t)(b * Tt + t0)) * Cc + kb, Cc, tid);
            CP_COMMIT();
        }
        uint32_t abuf = base + stg * STAGEB;
        uint32_t bbuf = abuf + TILEB;
#pragma unroll
        for (int ks = 0; ks < 2; ks++) {
            uint32_t a[4][4], bf[2][4];
#pragma unroll
            for (int mi = 0; mi < 4; mi++) {
                uint32_t ad = abuf + (m0 + mi * 16 + (lane & 15)) * ROWB + ks * 32 + ((lane >> 4) << 4);
                LDMATRIX_X4(a[mi][0], a[mi][1], a[mi][2], a[mi][3], ad);
            }
#pragma unroll
            for (int np = 0; np < 2; np++) {
                uint32_t bd = bbuf + (n0 + np * 16 + (lane & 7) + ((lane >> 4) << 3)) * ROWB +
                              ks * 32 + (((lane >> 3) & 1) << 4);
                LDMATRIX_X4(bf[np][0], bf[np][1], bf[np][2], bf[np][3], bd);
            }
#pragma unroll
            for (int mi = 0; mi < 4; mi++)
#pragma unroll
                for (int ni = 0; ni < 4; ni++) {
                    int np = ni >> 1, pp = (ni & 1) << 1;
                    MMA16816(acc[mi][ni][0], acc[mi][ni][1], acc[mi][ni][2], acc[mi][ni][3],
                             a[mi][0], a[mi][1], a[mi][2], a[mi][3], bf[np][pp], bf[np][pp + 1]);
                }
        }
        stg = (stg + 1 == NSTAGE) ? 0 : stg + 1;
    }

#pragma unroll
    for (int mi = 0; mi < 4; mi++)
#pragma unroll
        for (int ni = 0; ni < 4; ni++) {
            int row = cm + m0 + mi * 16 + (lane >> 2);       // c
            int col = t0 + n0 + ni * 8 + ((lane & 3) << 1);  // t
            float m0v = g_mean[b * Tt + col];
            float m1v = g_mean[b * Tt + col + 1];
            *(float2*)&out[((size_t)(b * Cc + row)) * Tt + col] =
                make_float2(acc[mi][ni][0] + m0v, acc[mi][ni][1] + m1v);
            *(float2*)&out[((size_t)(b * Cc + row + 8)) * Tt + col] =
                make_float2(acc[mi][ni][2] + m0v, acc[mi][ni][3] + m1v);
        }
}

// ---------------------------------------------------------------------------
extern "C" void kernel_launch(void* const* d_in, const int* in_sizes, int n_in,
                              void* d_out, int out_size) {
    const float* x = (const float*)d_in[0];
    const float* qw = (const float*)d_in[1];
    const float* qb = (const float*)d_in[2];
    const float* kw = (const float*)d_in[3];
    const float* kb = (const float*)d_in[4];
    float* out = (float*)d_out;
    float* attn = out + (size_t)Bb * Cc * Tt;  // outputs packed: (out, attn)

    cudaFuncSetAttribute(cov_mma_kernel, cudaFuncAttributeMaxDynamicSharedMemorySize, SMEM_DYN);
    cudaFuncSetAttribute(out_mma_kernel, cudaFuncAttributeMaxDynamicSharedMemorySize, SMEM_DYN);

    stats_tr_kernel<<<dim3(Tt / 32, Bb), 256>>>(x);
    denom_kernel<<<Bb, 256>>>();
    cov_mma_kernel<<<dim3(2, 2, Bb * SPLIT), 256, SMEM_DYN>>>();
    pcc_kernel<<<(Bb * Cc * Cc) / 256, 256>>>();
    qk_kernel<<<dim3(Cc / 64, Bb), 256>>>(qw, qb, kw, kb);
    attn_kernel<<<dim3(Cc / 16, Bb), 256>>>(attn);
    out_mma_kernel<<<dim3(Tt / 128, Cc / 128, Bb), 256, SMEM_DYN>>>(out);
}

// round 7
// speedup vs baseline: 2.0206x; 1.3562x over previous
#include <cuda_runtime.h>
#include <cuda_bf16.h>
#include <cstdint>
#include <math.h>

#define Bb 16
#define Cc 256
#define Tt 8192
#define Ee 32
#define SPLIT 2

// ===== scratch (device globals; no allocation allowed) =====
__device__ float g_mean[Bb * Tt];
__device__ float g_var[Bb * Tt];
__device__ float g_invdenom[Bb];
__device__ float g_part[SPLIT][Bb * Cc * Cc];
__device__ float g_pcc[Bb * Cc * Cc];
__device__ float g_q[Bb * Cc * Ee];
__device__ float g_k[Bb * Cc * Ee];
__device__ __nv_bfloat16 g_cthi[Bb * Cc * Tt];    // centered x, t-major, hi
__device__ __nv_bfloat16 g_ctlo2[Bb * Cc * Tt];   // centered x, t-major, 2*lo (for cov symmetry trick)
__device__ __nv_bfloat16 g_cthiT[Bb * Tt * Cc];   // centered x, c-major (transposed), hi
__device__ __nv_bfloat16 g_ctloT[Bb * Tt * Cc];   // centered x, c-major, lo (plain)
__device__ __nv_bfloat16 g_ahi[Bb * Cc * Cc];     // attn hi
__device__ __nv_bfloat16 g_alo[Bb * Cc * Cc];     // attn lo

// ===== helpers =====
__device__ __forceinline__ uint32_t smem_u32(const void* p) {
    uint32_t a;
    asm("{ .reg .u64 t; cvta.to.shared.u64 t, %1; cvt.u32.u64 %0, t; }" : "=r"(a) : "l"(p));
    return a;
}
#define CP_ASYNC16(dst, src) \
    asm volatile("cp.async.cg.shared.global [%0], [%1], 16;" :: "r"(dst), "l"(src))
#define CP_COMMIT() asm volatile("cp.async.commit_group;" ::: "memory")
#define CP_WAIT1() asm volatile("cp.async.wait_group 1;" ::: "memory")
#define CP_WAIT0() asm volatile("cp.async.wait_group 0;" ::: "memory")

#define LDMATRIX_X4(r0, r1, r2, r3, a) \
    asm volatile("ldmatrix.sync.aligned.m8n8.x4.shared.b16 {%0,%1,%2,%3}, [%4];" \
        : "=r"(r0), "=r"(r1), "=r"(r2), "=r"(r3) : "r"(a))

#define MMA16816(c0, c1, c2, c3, a0, a1, a2, a3, b0, b1) \
    asm volatile("mma.sync.aligned.m16n8k16.row.col.f32.bf16.bf16.f32 " \
        "{%0,%1,%2,%3}, {%4,%5,%6,%7}, {%8,%9}, {%0,%1,%2,%3};" \
        : "+f"(c0), "+f"(c1), "+f"(c2), "+f"(c3) \
        : "r"(a0), "r"(a1), "r"(a2), "r"(a3), "r"(b0), "r"(b1))

// smem tile: 128 rows x 64 bf16 (128B) + 16B pad -> 144B row stride (odd 16B units: conflict-free)
#define ROWB 144
#define TILEB (128 * ROWB)       // 18432
#define STAGEB (2 * TILEB)
#define NSTAGE 3
#define SMEM_DYN (NSTAGE * STAGEB)

// load one 128x64 bf16 tile (K-major, rowStride elems) into smem at sbuf
__device__ __forceinline__ void load_tile(uint32_t sbuf, const __nv_bfloat16* gbase,
                                          size_t rowStride, int tid) {
#pragma unroll
    for (int i = tid; i < 1024; i += 256) {
        int r = i >> 3, s = i & 7;
        CP_ASYNC16(sbuf + r * ROWB + s * 16, gbase + (size_t)r * rowStride + s * 8);
    }
}

// shared MMA tile body: consumes stage at (abuf,bbuf), BK=64
__device__ __forceinline__ void mma_chunk(uint32_t abuf, uint32_t bbuf, int m0, int n0,
                                          int lane, float acc[4][4][4]) {
#pragma unroll
    for (int ks = 0; ks < 4; ks++) {
        uint32_t a[4][4], bf[2][4];
#pragma unroll
        for (int mi = 0; mi < 4; mi++) {
            uint32_t ad = abuf + (m0 + mi * 16 + (lane & 15)) * ROWB + ks * 32 + ((lane >> 4) << 4);
            LDMATRIX_X4(a[mi][0], a[mi][1], a[mi][2], a[mi][3], ad);
        }
#pragma unroll
        for (int np = 0; np < 2; np++) {
            uint32_t bd = bbuf + (n0 + np * 16 + (lane & 7) + ((lane >> 4) << 3)) * ROWB +
                          ks * 32 + (((lane >> 3) & 1) << 4);
            LDMATRIX_X4(bf[np][0], bf[np][1], bf[np][2], bf[np][3], bd);
        }
#pragma unroll
        for (int mi = 0; mi < 4; mi++)
#pragma unroll
            for (int ni = 0; ni < 4; ni++) {
                int np = ni >> 1, pp = (ni & 1) << 1;
                MMA16816(acc[mi][ni][0], acc[mi][ni][1], acc[mi][ni][2], acc[mi][ni][3],
                         a[mi][0], a[mi][1], a[mi][2], a[mi][3], bf[np][pp], bf[np][pp + 1]);
            }
    }
}

// ---------------------------------------------------------------------------
// 1) stats + centered bf16 hi/lo emission (both layouts), 32 t x 256 c tiles
// ---------------------------------------------------------------------------
__global__ void __launch_bounds__(256) stats_tr_kernel(const float* __restrict__ x) {
    __shared__ float xs[Cc][33];
    __shared__ float ps[8][33], pq[8][33];
    __shared__ float ms[32];
    int b = blockIdx.y;
    int t0 = blockIdx.x * 32;
    int tid = threadIdx.x;

    for (int idx = tid; idx < Cc * 32; idx += 256) {
        int c = idx >> 5, tt = idx & 31;
        xs[c][tt] = x[((size_t)(b * Cc + c)) * Tt + t0 + tt];
    }
    __syncthreads();
    {
        int tt = tid & 31, g = tid >> 5;
        float s = 0.f, sq = 0.f;
#pragma unroll
        for (int c = g * 32; c < g * 32 + 32; c++) {
            float v = xs[c][tt];
            s += v; sq += v * v;
        }
        ps[g][tt] = s; pq[g][tt] = sq;
    }
    __syncthreads();
    if (tid < 32) {
        float s = 0.f, sq = 0.f;
#pragma unroll
        for (int g = 0; g < 8; g++) { s += ps[g][tid]; sq += pq[g][tid]; }
        float m = s * (1.0f / Cc);
        ms[tid] = m;
        g_mean[b * Tt + t0 + tid] = m;
        g_var[b * Tt + t0 + tid] = (sq - (float)Cc * m * m) * (1.0f / (Cc - 1));
    }
    __syncthreads();
    // t-major centered hi / 2*lo
    for (int idx = tid; idx < Cc * 32; idx += 256) {
        int c = idx >> 5, tt = idx & 31;
        float v = xs[c][tt] - ms[tt];
        __nv_bfloat16 h = __float2bfloat16(v);
        size_t o = ((size_t)(b * Cc + c)) * Tt + t0 + tt;
        g_cthi[o] = h;
        g_ctlo2[o] = __float2bfloat16(2.0f * (v - __bfloat162float(h)));
    }
    // c-major (transposed) centered hi/lo
    for (int idx = tid; idx < Cc * 32; idx += 256) {
        int tt = idx >> 8, c = idx & 255;
        float v = xs[c][tt] - ms[tt];
        __nv_bfloat16 h = __float2bfloat16(v);
        size_t o = ((size_t)(b * Tt + t0 + tt)) * Cc + c;
        g_cthiT[o] = h;
        g_ctloT[o] = __float2bfloat16(v - __bfloat162float(h));
    }
}

// ---------------------------------------------------------------------------
// 2) denom
// ---------------------------------------------------------------------------
__global__ void denom_kernel() {
    int b = blockIdx.x, tid = threadIdx.x;
    __shared__ float red[256];
    float a = 0.f;
    for (int t = tid; t < Tt; t += 256) a += g_var[b * Tt + t];
    red[tid] = a;
    __syncthreads();
    for (int o = 128; o > 0; o >>= 1) {
        if (tid < o) red[tid] += red[tid + o];
        __syncthreads();
    }
    if (tid == 0) g_invdenom[b] = 1.0f / red[0];
}

// ---------------------------------------------------------------------------
// 3) cov via mma.sync, 2 segments (symmetry trick): S = HiHi^T + 2 Hi Lo^T
// ---------------------------------------------------------------------------
__global__ void __launch_bounds__(256, 1) cov_mma_kernel() {
    extern __shared__ char dynsmem[];
    uint32_t base = smem_u32(dynsmem);
    int tid = threadIdx.x;
    int lane = tid & 31, wid = tid >> 5;
    int b = blockIdx.z >> 1;
    int sp = blockIdx.z & 1;
    int cm = blockIdx.y * 128;
    int cn = blockIdx.x * 128;
    int m0 = (wid & 1) * 64;
    int n0 = (wid >> 1) * 32;
    const int k0 = sp * (Tt / SPLIT);
    const int NSEG = (Tt / SPLIT) / 64;   // 64 chunks per segment
    const int NST = 2 * NSEG;             // 128

    const __nv_bfloat16* segA[2] = {g_cthi, g_cthi};
    const __nv_bfloat16* segB[2] = {g_cthi, g_ctlo2};

    float acc[4][4][4];
#pragma unroll
    for (int i = 0; i < 4; i++)
#pragma unroll
        for (int j = 0; j < 4; j++)
#pragma unroll
            for (int k = 0; k < 4; k++) acc[i][j][k] = 0.f;

#pragma unroll
    for (int p = 0; p < 2; p++) {
        int kb = k0 + p * 64;
        load_tile(base + p * STAGEB, segA[0] + ((size_t)(b * Cc + cm)) * Tt + kb, Tt, tid);
        load_tile(base + p * STAGEB + TILEB, segB[0] + ((size_t)(b * Cc + cn)) * Tt + kb, Tt, tid);
        CP_COMMIT();
    }

    int stg = 0;
    for (int ch = 0; ch < NST; ch++) {
        if (ch == NST - 1) { CP_WAIT0(); } else { CP_WAIT1(); }
        __syncthreads();
        if (ch + 2 < NST) {
            int nc = ch + 2;
            int seg = nc / NSEG;
            int kb = k0 + (nc % NSEG) * 64;
            int ns = (stg + 2 >= NSTAGE) ? (stg + 2 - NSTAGE) : (stg + 2);
            load_tile(base + ns * STAGEB, segA[seg] + ((size_t)(b * Cc + cm)) * Tt + kb, Tt, tid);
            load_tile(base + ns * STAGEB + TILEB, segB[seg] + ((size_t)(b * Cc + cn)) * Tt + kb, Tt, tid);
            CP_COMMIT();
        }
        mma_chunk(base + stg * STAGEB, base + stg * STAGEB + TILEB, m0, n0, lane, acc);
        stg = (stg + 1 == NSTAGE) ? 0 : stg + 1;
    }

    float* dst = g_part[sp] + ((size_t)b) * Cc * Cc;
#pragma unroll
    for (int mi = 0; mi < 4; mi++)
#pragma unroll
        for (int ni = 0; ni < 4; ni++) {
            int row = cm + m0 + mi * 16 + (lane >> 2);
            int col = cn + n0 + ni * 8 + ((lane & 3) << 1);
            *(float2*)&dst[(size_t)row * Cc + col] = make_float2(acc[mi][ni][0], acc[mi][ni][1]);
            *(float2*)&dst[(size_t)(row + 8) * Cc + col] = make_float2(acc[mi][ni][2], acc[mi][ni][3]);
        }
}

// ---------------------------------------------------------------------------
// 4) pcc = (S + S^T) * 0.5 * invdenom,  S = sum_s part[s]
// ---------------------------------------------------------------------------
__global__ void pcc_kernel() {
    int idx = blockIdx.x * 256 + threadIdx.x;
    int b = idx >> 16;
    int c = (idx >> 8) & 255, d = idx & 255;
    size_t tidx = ((size_t)b << 16) | (d << 8) | c;
    float a = g_part[0][idx] + g_part[1][idx] + g_part[0][tidx] + g_part[1][tidx];
    g_pcc[idx] = a * 0.5f * g_invdenom[b];
}

// ---------------------------------------------------------------------------
// 5) q/k projections (small fp32 SIMT GEMM)
// ---------------------------------------------------------------------------
__global__ void __launch_bounds__(256) qk_kernel(const float* __restrict__ qw,
                                                 const float* __restrict__ qb,
                                                 const float* __restrict__ kw,
                                                 const float* __restrict__ kb) {
    __shared__ float Ps[32][68];
    __shared__ float Ws[32][68];
    int b = blockIdx.y;
    int c0 = blockIdx.x * 64;
    int tid = threadIdx.x;
    int lr = tid >> 3, lq = tid & 7;
    int tx = tid & 15, ty = tid >> 4;
    const float* pb = g_pcc + (size_t)b * Cc * Cc;

    float acc[4][4];
#pragma unroll
    for (int i = 0; i < 4; i++)
#pragma unroll
        for (int j = 0; j < 4; j++) acc[i][j] = 0.f;

    for (int d0 = 0; d0 < Cc; d0 += 32) {
#pragma unroll
        for (int i = 0; i < 2; i++) {
            int r = lr + i * 32;
            float4 v = *(const float4*)&pb[(size_t)(c0 + r) * Cc + d0 + lq * 4];
            Ps[lq * 4 + 0][r] = v.x; Ps[lq * 4 + 1][r] = v.y;
            Ps[lq * 4 + 2][r] = v.z; Ps[lq * 4 + 3][r] = v.w;
            const float* wsrc = (r < 32) ? (qw + (size_t)r * Cc) : (kw + (size_t)(r - 32) * Cc);
            float4 w = *(const float4*)&wsrc[d0 + lq * 4];
            Ws[lq * 4 + 0][r] = w.x; Ws[lq * 4 + 1][r] = w.y;
            Ws[lq * 4 + 2][r] = w.z; Ws[lq * 4 + 3][r] = w.w;
        }
        __syncthreads();
#pragma unroll
        for (int k = 0; k < 32; k++) {
            float a[4], bbv[4];
            *(float4*)(a) = *(const float4*)&Ps[k][ty * 4];
            *(float4*)(bbv) = *(const float4*)&Ws[k][tx * 4];
#pragma unroll
            for (int i = 0; i < 4; i++)
#pragma unroll
                for (int j = 0; j < 4; j++) acc[i][j] += a[i] * bbv[j];
        }
        __syncthreads();
    }
#pragma unroll
    for (int i = 0; i < 4; i++) {
        int c = c0 + ty * 4 + i;
#pragma unroll
        for (int j = 0; j < 4; j++) {
            int e = tx * 4 + j;
            if (e < 32) g_q[((size_t)b * Cc + c) * Ee + e] = acc[i][j] + qb[e];
            else g_k[((size_t)b * Cc + c) * Ee + (e - 32)] = acc[i][j] + kb[e - 32];
        }
    }
}

// ---------------------------------------------------------------------------
// 6) softmax: warp-per-row, shuffle reductions (no syncs in loop)
//    grid (Cc/32, Bb), block 256 = 8 warps; warp handles 4 rows
// ---------------------------------------------------------------------------
__global__ void __launch_bounds__(256) attn_kernel(float* __restrict__ attn_out) {
    __shared__ float ks[Cc][33];
    __shared__ float qs[32][33];
    int b = blockIdx.y;
    int c0 = blockIdx.x * 32;
    int tid = threadIdx.x;
    int lane = tid & 31, wid = tid >> 5;

    const float* kbp = g_k + (size_t)b * Cc * Ee;
    for (int idx = tid; idx < Cc * Ee; idx += 256) ks[idx >> 5][idx & 31] = kbp[idx];
    const float* qbp = g_q + ((size_t)b * Cc + c0) * Ee;
    for (int idx = tid; idx < 32 * Ee; idx += 256) qs[idx >> 5][idx & 31] = qbp[idx];
    __syncthreads();

    float* ab = attn_out + (size_t)b * Cc * Cc;
    __nv_bfloat16* ahp = g_ahi + (size_t)b * Cc * Cc;
    __nv_bfloat16* alp = g_alo + (size_t)b * Cc * Cc;

    for (int rr = 0; rr < 4; rr++) {
        int r = wid * 4 + rr;  // local row 0..31
        float sc[8];
#pragma unroll
        for (int j = 0; j < 8; j++) sc[j] = 0.f;
#pragma unroll
        for (int e = 0; e < Ee; e++) {
            float qv = qs[r][e];
#pragma unroll
            for (int j = 0; j < 8; j++) sc[j] += qv * ks[j * 32 + lane][e];
        }
        float mx = -1e30f;
#pragma unroll
        for (int j = 0; j < 8; j++) { sc[j] *= 0.0625f; mx = fmaxf(mx, sc[j]); }
#pragma unroll
        for (int o = 16; o > 0; o >>= 1) mx = fmaxf(mx, __shfl_xor_sync(0xffffffffu, mx, o));
        float sum = 0.f;
#pragma unroll
        for (int j = 0; j < 8; j++) { sc[j] = expf(sc[j] - mx); sum += sc[j]; }
#pragma unroll
        for (int o = 16; o > 0; o >>= 1) sum += __shfl_xor_sync(0xffffffffu, sum, o);
        float inv = 1.0f / sum;
        size_t rowo = (size_t)(c0 + r) * Cc;
#pragma unroll
        for (int j = 0; j < 8; j++) {
            int d = j * 32 + lane;
            float av = sc[j] * inv;
            ab[rowo + d] = av;
            __nv_bfloat16 h = __float2bfloat16(av);
            ahp[rowo + d] = h;
            alp[rowo + d] = __float2bfloat16(av - __bfloat162float(h));
        }
    }
}

// ---------------------------------------------------------------------------
// 7) out via mma.sync (3 segs): out[c,t] = sum_d attn[c,d] ctT[t,d] + mean[t]
// ---------------------------------------------------------------------------
__global__ void __launch_bounds__(256, 1) out_mma_kernel(float* __restrict__ out) {
    extern __shared__ char dynsmem[];
    uint32_t base = smem_u32(dynsmem);
    int tid = threadIdx.x;
    int lane = tid & 31, wid = tid >> 5;
    int b = blockIdx.z;
    int cm = blockIdx.y * 128;
    int t0 = blockIdx.x * 128;
    int m0 = (wid & 1) * 64;
    int n0 = (wid >> 1) * 32;
    const int NST = 12;  // 3 segs x 4 chunks of BK=64 over K=256

    const __nv_bfloat16* segA[3] = {g_ahi, g_ahi, g_alo};
    const __nv_bfloat16* segB[3] = {g_cthiT, g_ctloT, g_cthiT};

    float acc[4][4][4];
#pragma unroll
    for (int i = 0; i < 4; i++)
#pragma unroll
        for (int j = 0; j < 4; j++)
#pragma unroll
            for (int k = 0; k < 4; k++) acc[i][j][k] = 0.f;

#pragma unroll
    for (int p = 0; p < 2; p++) {
        int kb = p * 64;
        load_tile(base + p * STAGEB, segA[0] + ((size_t)(b * Cc + cm)) * Cc + kb, Cc, tid);
        load_tile(base + p * STAGEB + TILEB, segB[0] + ((size_t)(b * Tt + t0)) * Cc + kb, Cc, tid);
        CP_COMMIT();
    }

    int stg = 0;
    for (int ch = 0; ch < NST; ch++) {
        if (ch == NST - 1) { CP_WAIT0(); } else { CP_WAIT1(); }
        __syncthreads();
        if (ch + 2 < NST) {
            int nc = ch + 2;
            int seg = nc >> 2;
            int kb = (nc & 3) * 64;
            int ns = (stg + 2 >= NSTAGE) ? (stg + 2 - NSTAGE) : (stg + 2);
            load_tile(base + ns * STAGEB, segA[seg] + ((size_t)(b * Cc + cm)) * Cc + kb, Cc, tid);
            load_tile(base + ns * STAGEB + TILEB, segB[seg] + ((size_t)(b * Tt + t0)) * Cc + kb, Cc, tid);
            CP_COMMIT();
        }
        mma_chunk(base + stg * STAGEB, base + stg * STAGEB + TILEB, m0, n0, lane, acc);
        stg = (stg + 1 == NSTAGE) ? 0 : stg + 1;
    }

#pragma unroll
    for (int mi = 0; mi < 4; mi++)
#pragma unroll
        for (int ni = 0; ni < 4; ni++) {
            int row = cm + m0 + mi * 16 + (lane >> 2);       // c
            int col = t0 + n0 + ni * 8 + ((lane & 3) << 1);  // t
            float m0v = g_mean[b * Tt + col];
            float m1v = g_mean[b * Tt + col + 1];
            *(float2*)&out[((size_t)(b * Cc + row)) * Tt + col] =
                make_float2(acc[mi][ni][0] + m0v, acc[mi][ni][1] + m1v);
            *(float2*)&out[((size_t)(b * Cc + row + 8)) * Tt + col] =
                make_float2(acc[mi][ni][2] + m0v, acc[mi][ni][3] + m1v);
        }
}

// ---------------------------------------------------------------------------
extern "C" void kernel_launch(void* const* d_in, const int* in_sizes, int n_in,
                              void* d_out, int out_size) {
    const float* x = (const float*)d_in[0];
    const float* qw = (const float*)d_in[1];
    const float* qb = (const float*)d_in[2];
    const float* kw = (const float*)d_in[3];
    const float* kb = (const float*)d_in[4];
    float* out = (float*)d_out;
    float* attn = out + (size_t)Bb * Cc * Tt;  // outputs packed: (out, attn)

    cudaFuncSetAttribute(cov_mma_kernel, cudaFuncAttributeMaxDynamicSharedMemorySize, SMEM_DYN);
    cudaFuncSetAttribute(out_mma_kernel, cudaFuncAttributeMaxDynamicSharedMemorySize, SMEM_DYN);

    stats_tr_kernel<<<dim3(Tt / 32, Bb), 256>>>(x);
    denom_kernel<<<Bb, 256>>>();
    cov_mma_kernel<<<dim3(2, 2, Bb * SPLIT), 256, SMEM_DYN>>>();
    pcc_kernel<<<(Bb * Cc * Cc) / 256, 256>>>();
    qk_kernel<<<dim3(Cc / 64, Bb), 256>>>(qw, qb, kw, kb);
    attn_kernel<<<dim3(Cc / 32, Bb), 256>>>(attn);
    out_mma_kernel<<<dim3(Tt / 128, Cc / 128, Bb), 256, SMEM_DYN>>>(out);
}

// round 9
// speedup vs baseline: 2.6090x; 1.2912x over previous
#include <cuda_runtime.h>
#include <cuda_bf16.h>
#include <cstdint>
#include <math.h>

#define Bb 16
#define Cc 256
#define Tt 8192
#define Ee 32
#define SPLIT 4

// ===== scratch (device globals; no allocation allowed) =====
__device__ float g_mean[Bb * Tt];
__device__ float g_var[Bb * Tt];
__device__ float g_invdenom[Bb];
__device__ float g_part[SPLIT][Bb * Cc * Cc];
__device__ float g_pcc[Bb * Cc * Cc];
__device__ float g_q[Bb * Cc * Ee];
__device__ float g_k[Bb * Cc * Ee];
__device__ __nv_bfloat16 g_cthi[Bb * Cc * Tt];    // centered x, t-major, hi
__device__ __nv_bfloat16 g_ctlo2[Bb * Cc * Tt];   // centered x, t-major, 2*lo
__device__ __nv_bfloat16 g_ahi[Bb * Cc * Cc];     // attn hi
__device__ __nv_bfloat16 g_alo[Bb * Cc * Cc];     // attn lo
__device__ __nv_bfloat16 g_ah2[Bb * Cc * Cc];     // 0.5 * attn hi (exact)

// ===== helpers =====
__device__ __forceinline__ uint32_t smem_u32(const void* p) {
    uint32_t a;
    asm("{ .reg .u64 t; cvta.to.shared.u64 t, %1; cvt.u32.u64 %0, t; }" : "=r"(a) : "l"(p));
    return a;
}
#define CP_ASYNC16(dst, src) \
    asm volatile("cp.async.cg.shared.global [%0], [%1], 16;" :: "r"(dst), "l"(src))
#define CP_COMMIT() asm volatile("cp.async.commit_group;" ::: "memory")
#define CP_WAIT1() asm volatile("cp.async.wait_group 1;" ::: "memory")
#define CP_WAIT0() asm volatile("cp.async.wait_group 0;" ::: "memory")

#define LDMATRIX_X4(r0, r1, r2, r3, a) \
    asm volatile("ldmatrix.sync.aligned.m8n8.x4.shared.b16 {%0,%1,%2,%3}, [%4];" \
        : "=r"(r0), "=r"(r1), "=r"(r2), "=r"(r3) : "r"(a))
#define LDMATRIX_X4T(r0, r1, r2, r3, a) \
    asm volatile("ldmatrix.sync.aligned.m8n8.x4.trans.shared.b16 {%0,%1,%2,%3}, [%4];" \
        : "=r"(r0), "=r"(r1), "=r"(r2), "=r"(r3) : "r"(a))

#define MMA16816(c0, c1, c2, c3, a0, a1, a2, a3, b0, b1) \
    asm volatile("mma.sync.aligned.m16n8k16.row.col.f32.bf16.bf16.f32 " \
        "{%0,%1,%2,%3}, {%4,%5,%6,%7}, {%8,%9}, {%0,%1,%2,%3};" \
        : "+f"(c0), "+f"(c1), "+f"(c2), "+f"(c3) \
        : "r"(a0), "r"(a1), "r"(a2), "r"(a3), "r"(b0), "r"(b1))

// K-major smem row: 64 bf16 (128B) + 16B pad = 144B (odd 16B units -> conflict-free)
#define ROWK 144
// t-major (trans) smem row: 256 bf16 (512B) + 16B pad = 528B (33 units, odd)
#define ROWT 528

// cov stage: B tile (256 x 64 K-major, Hi) + A tile (128 x 64, Lo2)
#define COV_BB (256 * ROWK)      // 36864
#define COV_AB (128 * ROWK)      // 18432
#define COV_STAGE (COV_BB + COV_AB)          // 55296
#define COV_SMEM (3 * COV_STAGE)             // 165888
// out stage: Bt tile (64 x 256 t-major) + 2 A tiles (128 x 64 K-major)
#define OUT_BB (64 * ROWT)       // 33792
#define OUT_AB (128 * ROWK)      // 18432
#define OUT_STAGE (OUT_BB + 2 * OUT_AB)      // 70656
#define OUT_SMEM (3 * OUT_STAGE)             // 211968

// ---- ldmatrix fragment loaders ----
// A: 64x16 slice (m0 rows base), K-major tile, non-trans
__device__ __forceinline__ void lds_A(uint32_t buf, int m0, int lane, int ks, uint32_t a[4][4]) {
#pragma unroll
    for (int mi = 0; mi < 4; mi++) {
        uint32_t ad = buf + (m0 + mi * 16 + (lane & 15)) * ROWK + ks * 32 + ((lane >> 4) << 4);
        LDMATRIX_X4(a[mi][0], a[mi][1], a[mi][2], a[mi][3], ad);
    }
}
// B: 64x16 slice from K-major [n][k] tile, non-trans
__device__ __forceinline__ void lds_Bn(uint32_t buf, int n0, int lane, int ks, uint32_t bf[4][4]) {
#pragma unroll
    for (int np = 0; np < 4; np++) {
        uint32_t bd = buf + (n0 + np * 16 + (lane & 7) + ((lane >> 4) << 3)) * ROWK +
                      ks * 32 + (((lane >> 3) & 1) << 4);
        LDMATRIX_X4(bf[np][0], bf[np][1], bf[np][2], bf[np][3], bd);
    }
}
// B: 64x16 slice from t-major [k][n] tile, trans (equivalent fragments to lds_Bn)
__device__ __forceinline__ void lds_Bt(uint32_t buf, int n0, int lane, int ks, uint32_t bf[4][4]) {
#pragma unroll
    for (int np = 0; np < 4; np++) {
        uint32_t bd = buf + (ks * 16 + (((lane >> 3) & 1) << 3) + (lane & 7)) * ROWT +
                      (n0 + np * 16 + ((lane >> 4) << 3)) * 2;
        LDMATRIX_X4T(bf[np][0], bf[np][1], bf[np][2], bf[np][3], bd);
    }
}
// 64x64 warp tile MMA: 32 mma.sync into acc[4][8][4]
__device__ __forceinline__ void mma_all(uint32_t a[4][4], uint32_t bf[4][4], float acc[4][8][4]) {
#pragma unroll
    for (int mi = 0; mi < 4; mi++)
#pragma unroll
        for (int ni = 0; ni < 8; ni++) {
            int np = ni >> 1, pp = (ni & 1) << 1;
            MMA16816(acc[mi][ni][0], acc[mi][ni][1], acc[mi][ni][2], acc[mi][ni][3],
                     a[mi][0], a[mi][1], a[mi][2], a[mi][3], bf[np][pp], bf[np][pp + 1]);
        }
}

// ---------------------------------------------------------------------------
// 1) stats + centered bf16 hi / 2*lo emission (t-major only)
// ---------------------------------------------------------------------------
__global__ void __launch_bounds__(256) stats_tr_kernel(const float* __restrict__ x) {
    __shared__ float xs[Cc][33];
    __shared__ float ps[8][33], pq[8][33];
    __shared__ float ms[32];
    int b = blockIdx.y;
    int t0 = blockIdx.x * 32;
    int tid = threadIdx.x;

    for (int idx = tid; idx < Cc * 32; idx += 256) {
        int c = idx >> 5, tt = idx & 31;
        xs[c][tt] = x[((size_t)(b * Cc + c)) * Tt + t0 + tt];
    }
    __syncthreads();
    {
        int tt = tid & 31, g = tid >> 5;
        float s = 0.f, sq = 0.f;
#pragma unroll
        for (int c = g * 32; c < g * 32 + 32; c++) {
            float v = xs[c][tt];
            s += v; sq += v * v;
        }
        ps[g][tt] = s; pq[g][tt] = sq;
    }
    __syncthreads();
    if (tid < 32) {
        float s = 0.f, sq = 0.f;
#pragma unroll
        for (int g = 0; g < 8; g++) { s += ps[g][tid]; sq += pq[g][tid]; }
        float m = s * (1.0f / Cc);
        ms[tid] = m;
        g_mean[b * Tt + t0 + tid] = m;
        g_var[b * Tt + t0 + tid] = (sq - (float)Cc * m * m) * (1.0f / (Cc - 1));
    }
    __syncthreads();
    for (int idx = tid; idx < Cc * 32; idx += 256) {
        int c = idx >> 5, tt = idx & 31;
        float v = xs[c][tt] - ms[tt];
        __nv_bfloat16 h = __float2bfloat16(v);
        size_t o = ((size_t)(b * Cc + c)) * Tt + t0 + tt;
        g_cthi[o] = h;
        g_ctlo2[o] = __float2bfloat16(2.0f * (v - __bfloat162float(h)));
    }
}

// ---------------------------------------------------------------------------
// 2) denom
// ---------------------------------------------------------------------------
__global__ void denom_kernel() {
    int b = blockIdx.x, tid = threadIdx.x;
    __shared__ float red[256];
    float a = 0.f;
    for (int t = tid; t < Tt; t += 256) a += g_var[b * Tt + t];
    red[tid] = a;
    __syncthreads();
    for (int o = 128; o > 0; o >>= 1) {
        if (tid < o) red[tid] += red[tid + o];
        __syncthreads();
    }
    if (tid == 0) g_invdenom[b] = 1.0f / red[0];
}

// ---------------------------------------------------------------------------
// 3) cov: S = Hi Hi^T + Lo2 Hi^T  (B=Hi shared; A seg0 aliases B tile)
//    CTA 128x256, 8 warps 2x4, warp 64x64, BK=64, 3-stage cp.async
//    grid (2 cm, SPLIT, Bb)
// ---------------------------------------------------------------------------
__global__ void __launch_bounds__(256, 1) cov_mma_kernel() {
    extern __shared__ char dynsmem[];
    uint32_t base = smem_u32(dynsmem);
    int tid = threadIdx.x;
    int lane = tid & 31, wid = tid >> 5;
    int cm = blockIdx.x * 128;
    int sp = blockIdx.y;
    int b = blockIdx.z;
    int m0 = (wid & 1) * 64;
    int n0 = (wid >> 1) * 64;
    const int k0 = sp * (Tt / SPLIT);
    const int NCH = (Tt / SPLIT) / 64;   // 32 chunks

    float acc[4][8][4];
#pragma unroll
    for (int i = 0; i < 4; i++)
#pragma unroll
        for (int j = 0; j < 8; j++)
#pragma unroll
            for (int k = 0; k < 4; k++) acc[i][j][k] = 0.f;

    // chunk loader: B = Hi rows 0..255; A = Lo2 rows cm..cm+127
    auto load_chunk = [&](int ch, int stg) {
        int kb = k0 + ch * 64;
        uint32_t bbuf = base + stg * COV_STAGE;
        const __nv_bfloat16* hb = g_cthi + ((size_t)(b * Cc)) * Tt + kb;
        for (int i = tid; i < 2048; i += 256) {
            int r = i >> 3, s = i & 7;
            CP_ASYNC16(bbuf + r * ROWK + s * 16, hb + (size_t)r * Tt + s * 8);
        }
        uint32_t abuf = bbuf + COV_BB;
        const __nv_bfloat16* lb = g_ctlo2 + ((size_t)(b * Cc + cm)) * Tt + kb;
        for (int i = tid; i < 1024; i += 256) {
            int r = i >> 3, s = i & 7;
            CP_ASYNC16(abuf + r * ROWK + s * 16, lb + (size_t)r * Tt + s * 8);
        }
        CP_COMMIT();
    };

    load_chunk(0, 0);
    load_chunk(1, 1);

    int stg = 0;
    for (int ch = 0; ch < NCH; ch++) {
        if (ch == NCH - 1) { CP_WAIT0(); } else { CP_WAIT1(); }
        __syncthreads();
        if (ch + 2 < NCH) {
            int ns = (stg + 2 >= 3) ? (stg + 2 - 3) : (stg + 2);
            load_chunk(ch + 2, ns);
        }
        uint32_t bbuf = base + stg * COV_STAGE;
        uint32_t abuf = bbuf + COV_BB;
#pragma unroll
        for (int ks = 0; ks < 4; ks++) {
            uint32_t bf[4][4], a[4][4];
            lds_Bn(bbuf, n0, lane, ks, bf);
            lds_A(bbuf, cm + m0, lane, ks, a);   // seg0: A = Hi (alias into B tile)
            mma_all(a, bf, acc);
            lds_A(abuf, m0, lane, ks, a);        // seg1: A = Lo2
            mma_all(a, bf, acc);
        }
        stg = (stg + 1 == 3) ? 0 : stg + 1;
    }

    float* dst = g_part[sp] + ((size_t)b) * Cc * Cc;
#pragma unroll
    for (int mi = 0; mi < 4; mi++)
#pragma unroll
        for (int ni = 0; ni < 8; ni++) {
            int row = cm + m0 + mi * 16 + (lane >> 2);
            int col = n0 + ni * 8 + ((lane & 3) << 1);
            *(float2*)&dst[(size_t)row * Cc + col] = make_float2(acc[mi][ni][0], acc[mi][ni][1]);
            *(float2*)&dst[(size_t)(row + 8) * Cc + col] = make_float2(acc[mi][ni][2], acc[mi][ni][3]);
        }
}

// ---------------------------------------------------------------------------
// 4) pcc = (S + S^T) * 0.5 * invdenom via tiled transpose (coalesced)
//    grid (64, Bb): 8x8 tiles of 32x32; block 256 = 32 cols x 8 rows
// ---------------------------------------------------------------------------
__global__ void __launch_bounds__(256) pcc_kernel() {
    __shared__ float s1[32][33], s2[32][33];
    int b = blockIdx.y;
    int ti = blockIdx.x >> 3, tj = blockIdx.x & 7;
    int tid = threadIdx.x;
    int col = tid & 31, r0 = tid >> 5;
    size_t bo = (size_t)b << 16;

#pragma unroll
    for (int rr = 0; rr < 4; rr++) {
        int r = r0 + rr * 8;
        size_t i1 = bo + (size_t)(ti * 32 + r) * Cc + tj * 32 + col;
        size_t i2 = bo + (size_t)(tj * 32 + r) * Cc + ti * 32 + col;
        float a1 = 0.f, a2 = 0.f;
#pragma unroll
        for (int s = 0; s < SPLIT; s++) { a1 += g_part[s][i1]; a2 += g_part[s][i2]; }
        s1[r][col] = a1;
        s2[r][col] = a2;
    }
    __syncthreads();
    float invd = 0.5f * g_invdenom[b];
#pragma unroll
    for (int rr = 0; rr < 4; rr++) {
        int r = r0 + rr * 8;
        g_pcc[bo + (size_t)(ti * 32 + r) * Cc + tj * 32 + col] =
            (s1[r][col] + s2[col][r]) * invd;
    }
}

// ---------------------------------------------------------------------------
// 5) q/k projections (small fp32 SIMT GEMM)
// ---------------------------------------------------------------------------
__global__ void __launch_bounds__(256) qk_kernel(const float* __restrict__ qw,
                                                 const float* __restrict__ qb,
                                                 const float* __restrict__ kw,
                                                 const float* __restrict__ kb) {
    __shared__ float Ps[32][68];
    __shared__ float Ws[32][68];
    int b = blockIdx.y;
    int c0 = blockIdx.x * 64;
    int tid = threadIdx.x;
    int lr = tid >> 3, lq = tid & 7;
    int tx = tid & 15, ty = tid >> 4;
    const float* pb = g_pcc + (size_t)b * Cc * Cc;

    float acc[4][4];
#pragma unroll
    for (int i = 0; i < 4; i++)
#pragma unroll
        for (int j = 0; j < 4; j++) acc[i][j] = 0.f;

    for (int d0 = 0; d0 < Cc; d0 += 32) {
#pragma unroll
        for (int i = 0; i < 2; i++) {
            int r = lr + i * 32;
            float4 v = *(const float4*)&pb[(size_t)(c0 + r) * Cc + d0 + lq * 4];
            Ps[lq * 4 + 0][r] = v.x; Ps[lq * 4 + 1][r] = v.y;
            Ps[lq * 4 + 2][r] = v.z; Ps[lq * 4 + 3][r] = v.w;
            const float* wsrc = (r < 32) ? (qw + (size_t)r * Cc) : (kw + (size_t)(r - 32) * Cc);
            float4 w = *(const float4*)&wsrc[d0 + lq * 4];
            Ws[lq * 4 + 0][r] = w.x; Ws[lq * 4 + 1][r] = w.y;
            Ws[lq * 4 + 2][r] = w.z; Ws[lq * 4 + 3][r] = w.w;
        }
        __syncthreads();
#pragma unroll
        for (int k = 0; k < 32; k++) {
            float a[4], bbv[4];
            *(float4*)(a) = *(const float4*)&Ps[k][ty * 4];
            *(float4*)(bbv) = *(const float4*)&Ws[k][tx * 4];
#pragma unroll
            for (int i = 0; i < 4; i++)
#pragma unroll
                for (int j = 0; j < 4; j++) acc[i][j] += a[i] * bbv[j];
        }
        __syncthreads();
    }
#pragma unroll
    for (int i = 0; i < 4; i++) {
        int c = c0 + ty * 4 + i;
#pragma unroll
        for (int j = 0; j < 4; j++) {
            int e = tx * 4 + j;
            if (e < 32) g_q[((size_t)b * Cc + c) * Ee + e] = acc[i][j] + qb[e];
            else g_k[((size_t)b * Cc + c) * Ee + (e - 32)] = acc[i][j] + kb[e - 32];
        }
    }
}

// ---------------------------------------------------------------------------
// 6) softmax: warp-per-row shuffle reductions; emits attn fp32 + ahi/alo/ah2
// ---------------------------------------------------------------------------
__global__ void __launch_bounds__(256) attn_kernel(float* __restrict__ attn_out) {
    __shared__ float ks[Cc][33];
    __shared__ float qs[32][33];
    int b = blockIdx.y;
    int c0 = blockIdx.x * 32;
    int tid = threadIdx.x;
    int lane = tid & 31, wid = tid >> 5;

    const float* kbp = g_k + (size_t)b * Cc * Ee;
    for (int idx = tid; idx < Cc * Ee; idx += 256) ks[idx >> 5][idx & 31] = kbp[idx];
    const float* qbp = g_q + ((size_t)b * Cc + c0) * Ee;
    for (int idx = tid; idx < 32 * Ee; idx += 256) qs[idx >> 5][idx & 31] = qbp[idx];
    __syncthreads();

    float* ab = attn_out + (size_t)b * Cc * Cc;
    __nv_bfloat16* ahp = g_ahi + (size_t)b * Cc * Cc;
    __nv_bfloat16* alp = g_alo + (size_t)b * Cc * Cc;
    __nv_bfloat16* a2p = g_ah2 + (size_t)b * Cc * Cc;

    for (int rr = 0; rr < 4; rr++) {
        int r = wid * 4 + rr;
        float sc[8];
#pragma unroll
        for (int j = 0; j < 8; j++) sc[j] = 0.f;
#pragma unroll
        for (int e = 0; e < Ee; e++) {
            float qv = qs[r][e];
#pragma unroll
            for (int j = 0; j < 8; j++) sc[j] += qv * ks[j * 32 + lane][e];
        }
        float mx = -1e30f;
#pragma unroll
        for (int j = 0; j < 8; j++) { sc[j] *= 0.0625f; mx = fmaxf(mx, sc[j]); }
#pragma unroll
        for (int o = 16; o > 0; o >>= 1) mx = fmaxf(mx, __shfl_xor_sync(0xffffffffu, mx, o));
        float sum = 0.f;
#pragma unroll
        for (int j = 0; j < 8; j++) { sc[j] = expf(sc[j] - mx); sum += sc[j]; }
#pragma unroll
        for (int o = 16; o > 0; o >>= 1) sum += __shfl_xor_sync(0xffffffffu, sum, o);
        float inv = 1.0f / sum;
        size_t rowo = (size_t)(c0 + r) * Cc;
#pragma unroll
        for (int j = 0; j < 8; j++) {
            int d = j * 32 + lane;
            float av = sc[j] * inv;
            ab[rowo + d] = av;
            __nv_bfloat16 h = __float2bfloat16(av);
            float hf = __bfloat162float(h);
            ahp[rowo + d] = h;
            alp[rowo + d] = __float2bfloat16(av - hf);
            a2p[rowo + d] = __float2bfloat16(0.5f * hf);  // exact (exponent shift)
        }
    }
}

// ---------------------------------------------------------------------------
// 7) out = ahi*Hi + alo*Hi + ah2*Lo2 + mean  (B via ldmatrix.trans from t-major)
//    CTA 128x256 (c x t), 8 warps 2x4, warp 64x64
//    chunks: 4 d-chunks x 2 types (type0: B=Hi + {ahi, alo}; type1: B=Lo2 + ah2)
//    grid (Tt/256, 2, Bb)
// ---------------------------------------------------------------------------
__global__ void __launch_bounds__(256, 1) out_mma_kernel(float* __restrict__ out) {
    extern __shared__ char dynsmem[];
    uint32_t base = smem_u32(dynsmem);
    int tid = threadIdx.x;
    int lane = tid & 31, wid = tid >> 5;
    int t0 = blockIdx.x * 256;
    int cm = blockIdx.y * 128;
    int b = blockIdx.z;
    int m0 = (wid & 1) * 64;
    int n0 = (wid >> 1) * 64;
    const int NCH = 8;

    float acc[4][8][4];
#pragma unroll
    for (int i = 0; i < 4; i++)
#pragma unroll
        for (int j = 0; j < 8; j++)
#pragma unroll
            for (int k = 0; k < 4; k++) acc[i][j][k] = 0.f;

    auto load_chunk = [&](int ch, int stg) {
        int d0 = (ch >> 1) * 64;
        int type = ch & 1;
        uint32_t bbuf = base + stg * OUT_STAGE;
        const __nv_bfloat16* bt = (type ? g_ctlo2 : g_cthi) + ((size_t)(b * Cc + d0)) * Tt + t0;
        for (int i = tid; i < 2048; i += 256) {
            int r = i >> 5, s = i & 31;
            CP_ASYNC16(bbuf + r * ROWT + s * 16, bt + (size_t)r * Tt + s * 8);
        }
        uint32_t a0 = bbuf + OUT_BB;
        if (type == 0) {
            const __nv_bfloat16* ah = g_ahi + ((size_t)(b * Cc + cm)) * Cc + d0;
            for (int i = tid; i < 1024; i += 256) {
                int r = i >> 3, s = i & 7;
                CP_ASYNC16(a0 + r * ROWK + s * 16, ah + r * Cc + s * 8);
            }
            const __nv_bfloat16* al = g_alo + ((size_t)(b * Cc + cm)) * Cc + d0;
            uint32_t a1 = a0 + OUT_AB;
            for (int i = tid; i < 1024; i += 256) {
                int r = i >> 3, s = i & 7;
                CP_ASYNC16(a1 + r * ROWK + s * 16, al + r * Cc + s * 8);
            }
        } else {
            const __nv_bfloat16* a2 = g_ah2 + ((size_t)(b * Cc + cm)) * Cc + d0;
            for (int i = tid; i < 1024; i += 256) {
                int r = i >> 3, s = i & 7;
                CP_ASYNC16(a0 + r * ROWK + s * 16, a2 + r * Cc + s * 8);
            }
        }
        CP_COMMIT();
    };

    load_chunk(0, 0);
    load_chunk(1, 1);

    int stg = 0;
    for (int ch = 0; ch < NCH; ch++) {
        if (ch == NCH - 1) { CP_WAIT0(); } else { CP_WAIT1(); }
        __syncthreads();
        if (ch + 2 < NCH) {
            int ns = (stg + 2 >= 3) ? (stg + 2 - 3) : (stg + 2);
            load_chunk(ch + 2, ns);
        }
        uint32_t bbuf = base + stg * OUT_STAGE;
        uint32_t a0buf = bbuf + OUT_BB;
        int type = ch & 1;
#pragma unroll
        for (int ks = 0; ks < 4; ks++) {
            uint32_t bf[4][4], a[4][4];
            lds_Bt(bbuf, n0, lane, ks, bf);
            lds_A(a0buf, m0, lane, ks, a);
            mma_all(a, bf, acc);
            if (type == 0) {
                lds_A(a0buf + OUT_AB, m0, lane, ks, a);
                mma_all(a, bf, acc);
            }
        }
        stg = (stg + 1 == 3) ? 0 : stg + 1;
    }

#pragma unroll
    for (int mi = 0; mi < 4; mi++)
#pragma unroll
        for (int ni = 0; ni < 8; ni++) {
            int row = cm + m0 + mi * 16 + (lane >> 2);       // c
            int col = t0 + n0 + ni * 8 + ((lane & 3) << 1);  // t
            float m0v = g_mean[b * Tt + col];
            float m1v = g_mean[b * Tt + col + 1];
            *(float2*)&out[((size_t)(b * Cc + row)) * Tt + col] =
                make_float2(acc[mi][ni][0] + m0v, acc[mi][ni][1] + m1v);
            *(float2*)&out[((size_t)(b * Cc + row + 8)) * Tt + col] =
                make_float2(acc[mi][ni][2] + m0v, acc[mi][ni][3] + m1v);
        }
}

// ---------------------------------------------------------------------------
extern "C" void kernel_launch(void* const* d_in, const int* in_sizes, int n_in,
                              void* d_out, int out_size) {
    const float* x = (const float*)d_in[0];
    const float* qw = (const float*)d_in[1];
    const float* qb = (const float*)d_in[2];
    const float* kw = (const float*)d_in[3];
    const float* kb = (const float*)d_in[4];
    float* out = (float*)d_out;
    float* attn = out + (size_t)Bb * Cc * Tt;  // outputs packed: (out, attn)

    cudaFuncSetAttribute(cov_mma_kernel, cudaFuncAttributeMaxDynamicSharedMemorySize, COV_SMEM);
    cudaFuncSetAttribute(out_mma_kernel, cudaFuncAttributeMaxDynamicSharedMemorySize, OUT_SMEM);

    stats_tr_kernel<<<dim3(Tt / 32, Bb), 256>>>(x);
    denom_kernel<<<Bb, 256>>>();
    cov_mma_kernel<<<dim3(2, SPLIT, Bb), 256, COV_SMEM>>>();
    pcc_kernel<<<dim3(64, Bb), 256>>>();
    qk_kernel<<<dim3(Cc / 64, Bb), 256>>>(qw, qb, kw, kb);
    attn_kernel<<<dim3(Cc / 32, Bb), 256>>>(attn);
    out_mma_kernel<<<dim3(Tt / 256, Cc / 128, Bb), 256, OUT_SMEM>>>(out);
}